// round 1
// baseline (speedup 1.0000x reference)
#include <cuda_runtime.h>

#define D      256
#define NB     30
#define EPG    240
#define NGRAPH 2048
#define NE     (NGRAPH * EPG)
#define NSEM   11

// ---------------- device scratch (no allocation allowed) ----------------
static __device__ float d_Wg2[5 * D];        // W_geo @ W_lot[0:256]
static __device__ float d_biasA[D];          // b_geo @ W_lot[0:256] + b_lot
static __device__ float d_tab2[NSEM * D];    // emb @ W_lot[256:512]
static __device__ float d_gcat[NGRAPH * 4 * D];  // [g0|g1|g2|g3] per graph

// ---------------- packed f32x2 helpers ----------------
__device__ __forceinline__ unsigned long long pk2(float lo, float hi) {
    unsigned long long r;
    asm("mov.b64 %0,{%1,%2};" : "=l"(r) : "f"(lo), "f"(hi));
    return r;
}
__device__ __forceinline__ void upk2(unsigned long long p, float& lo, float& hi) {
    asm("mov.b64 {%0,%1},%2;" : "=f"(lo), "=f"(hi) : "l"(p));
}
__device__ __forceinline__ unsigned long long ffma2(unsigned long long a,
                                                    unsigned long long b,
                                                    unsigned long long c) {
    unsigned long long d_;
    asm("fma.rn.f32x2 %0,%1,%2,%3;" : "=l"(d_) : "l"(a), "l"(b), "l"(c));
    return d_;
}

// ---------------- precompute: fold encoder weights ----------------
// 17 blocks x 256 threads. Rows 0..4: W_geo@W_A; row 5: bias; rows 6..16: emb@W_B.
__global__ void precompute_kernel(const float* __restrict__ Wgeo,
                                  const float* __restrict__ bgeo,
                                  const float* __restrict__ emb,
                                  const float* __restrict__ Wlot,
                                  const float* __restrict__ blot) {
    const int r = blockIdx.x, t = threadIdx.x;
    float acc = 0.f;
    if (r < 5) {
        for (int k = 0; k < D; k++) acc = fmaf(Wgeo[r * D + k], Wlot[k * D + t], acc);
        d_Wg2[r * D + t] = acc;
    } else if (r == 5) {
        for (int k = 0; k < D; k++) acc = fmaf(bgeo[k], Wlot[k * D + t], acc);
        d_biasA[t] = acc + blot[t];
    } else {
        const int s = r - 6;
        for (int k = 0; k < D; k++) acc = fmaf(emb[s * D + k], Wlot[(D + k) * D + t], acc);
        d_tab2[s * D + t] = acc;
    }
}

// ---------------- main fused kernel: one CTA per graph ----------------
// SMEM layout (floats):
#define SM_H   0        // h[30][256]
#define SM_A   7680     // agg[30][256]
#define SM_INV 15360    // inv count [30] (+2 pad)
#define SM_GEO 15392    // geometry [30*5] (+10 pad)
#define SM_SEM 15552    // semantic ints [30] (+2 pad)
#define SM_ES  15584    // local src [240]
#define SM_ED  15824    // local dst [240]
#define SM_FLOATS 16064

__global__ __launch_bounds__(256, 2)
void gnn_main(const float* __restrict__ geometry, const int* __restrict__ semantic,
              const int* __restrict__ esrc_g, const int* __restrict__ edst_g,
              const float* __restrict__ Wlot,
              const float* __restrict__ W1, const float* __restrict__ b1,
              const float* __restrict__ W2, const float* __restrict__ b2,
              const float* __restrict__ W3, const float* __restrict__ b3) {
    extern __shared__ float smem[];
    const int b = blockIdx.x, t = threadIdx.x;
    float* sh_h   = smem + SM_H;
    float* sh_a   = smem + SM_A;
    float* sh_inv = smem + SM_INV;
    float* sh_geo = smem + SM_GEO;
    int*   sh_sem = (int*)(smem + SM_SEM);
    int*   sh_es  = (int*)(smem + SM_ES);
    int*   sh_ed  = (int*)(smem + SM_ED);

    // ---- load per-graph metadata ----
    if (t < NB) { sh_inv[t] = 0.f; sh_sem[t] = semantic[b * NB + t]; }
    if (t < EPG) {
        sh_es[t] = esrc_g[b * EPG + t] - b * NB;
        sh_ed[t] = edst_g[b * EPG + t] - b * NB;
    }
    if (t < NB * 5) sh_geo[t] = geometry[b * NB * 5 + t];
    __syncthreads();
    if (t < EPG) atomicAdd(&sh_inv[sh_ed[t]], 1.0f);
    __syncthreads();
    if (t < NB) { float c = sh_inv[t]; sh_inv[t] = (c > 0.f) ? (1.0f / c) : 0.f; }

    // ---- phase 1: h0 = relu(geo@Wg2 + tab2[sem] + W_lot[512+v] + biasA); g0 = colmax ----
    {
        float m = 0.f;
        const float ba = d_biasA[t];
        #pragma unroll
        for (int v = 0; v < NB; v++) {
            float acc = ba + d_tab2[sh_sem[v] * D + t] + Wlot[(2 * D + v) * D + t];
            #pragma unroll
            for (int j = 0; j < 5; j++)
                acc = fmaf(sh_geo[v * 5 + j], d_Wg2[j * D + t], acc);
            acc = fmaxf(acc, 0.f);  // relu >= 0, so max-init 0 is exact
            sh_h[v * D + t] = acc;
            m = fmaxf(m, acc);
        }
        d_gcat[b * (4 * D) + t] = m;
    }
    __syncthreads();

    // ---- 3 message-passing layers ----
    const float* Ws[3] = {W1, W2, W3};
    const float* bs[3] = {b1, b2, b3};

    for (int L = 0; L < 3; ++L) {
        // mean-aggregate h[src] at dst; thread t exclusively owns column t -> no races
        #pragma unroll
        for (int v = 0; v < NB; v++) sh_a[v * D + t] = 0.f;
        #pragma unroll 4
        for (int e = 0; e < EPG; e++) {
            const int s_ = sh_es[e], dd = sh_ed[e];
            sh_a[dd * D + t] += sh_h[s_ * D + t];
        }
        #pragma unroll
        for (int v = 0; v < NB; v++) sh_a[v * D + t] *= sh_inv[v];
        __syncthreads();

        // GEMM: acc[v] = h[v]@W_top[:,t] + agg[v]@W_bot[:,t], packed f32x2 over even/odd k
        unsigned long long acc2[NB];
        #pragma unroll
        for (int v = 0; v < NB; v++) acc2[v] = 0ULL;
        const float* Wc = Ws[L] + t;

        for (int k = 0; k < D; k += 4) {
            const unsigned long long w01 = pk2(Wc[(k    ) * D], Wc[(k + 1) * D]);
            const unsigned long long w23 = pk2(Wc[(k + 2) * D], Wc[(k + 3) * D]);
            #pragma unroll
            for (int v = 0; v < NB; v++) {
                const ulonglong2 x = *(const ulonglong2*)(sh_h + v * D + k);  // LDS.128 broadcast
                acc2[v] = ffma2(x.x, w01, acc2[v]);
                acc2[v] = ffma2(x.y, w23, acc2[v]);
            }
        }
        for (int k = 0; k < D; k += 4) {
            const unsigned long long w01 = pk2(Wc[(D + k    ) * D], Wc[(D + k + 1) * D]);
            const unsigned long long w23 = pk2(Wc[(D + k + 2) * D], Wc[(D + k + 3) * D]);
            #pragma unroll
            for (int v = 0; v < NB; v++) {
                const ulonglong2 x = *(const ulonglong2*)(sh_a + v * D + k);
                acc2[v] = ffma2(x.x, w01, acc2[v]);
                acc2[v] = ffma2(x.y, w23, acc2[v]);
            }
        }

        const float bias = bs[L][t];
        __syncthreads();  // all GEMM reads of sh_h complete before overwrite
        float m = 0.f;
        #pragma unroll
        for (int v = 0; v < NB; v++) {
            float lo, hi; upk2(acc2[v], lo, hi);
            float val = lo + hi + bias;
            val = fmaxf(val, 0.f);
            val = (sh_inv[v] > 0.f) ? val : 0.f;  // cnt==0 -> exactly 0 (matches s/max(cnt,1))
            sh_h[v * D + t] = val;
            m = fmaxf(m, val);
        }
        d_gcat[b * (4 * D) + (L + 1) * D + t] = m;
        __syncthreads();
    }
}

// ---------------- head: latent = g@W_agg+b; mu/logvar. 16 graphs per CTA ----------------
#define GPB 16
__global__ __launch_bounds__(256, 2)
void head_kernel(const float* __restrict__ Wagg, const float* __restrict__ bagg,
                 const float* __restrict__ Wmu, const float* __restrict__ bmu,
                 const float* __restrict__ Wvar, const float* __restrict__ bvar,
                 float* __restrict__ out) {
    extern __shared__ float smem[];
    float* sg   = smem;                // [GPB][1024]
    float* slat = smem + GPB * 1024;   // [GPB][256]
    const int t = threadIdx.x;
    const int b0 = blockIdx.x * GPB;

    for (int i = t; i < GPB * 1024; i += 256) sg[i] = d_gcat[b0 * 1024 + i];
    __syncthreads();

    float acc[GPB];
    {
        const float ba = bagg[t];
        #pragma unroll
        for (int g = 0; g < GPB; g++) acc[g] = ba;
    }
    for (int k = 0; k < 1024; k++) {
        const float w = Wagg[k * D + t];
        #pragma unroll
        for (int g = 0; g < GPB; g++) acc[g] = fmaf(sg[g * 1024 + k], w, acc[g]);
    }
    #pragma unroll
    for (int g = 0; g < GPB; g++) slat[g * D + t] = acc[g];
    __syncthreads();

    float mu[GPB], lv[GPB];
    const float bm = bmu[t], bv = bvar[t];
    #pragma unroll
    for (int g = 0; g < GPB; g++) { mu[g] = bm; lv[g] = bv; }
    for (int k = 0; k < D; k++) {
        const float wm = Wmu[k * D + t];
        const float wv = Wvar[k * D + t];
        #pragma unroll
        for (int g = 0; g < GPB; g++) {
            const float x = slat[g * D + k];
            mu[g] = fmaf(x, wm, mu[g]);
            lv[g] = fmaf(x, wv, lv[g]);
        }
    }
    #pragma unroll
    for (int g = 0; g < GPB; g++) {
        out[(b0 + g) * D + t]               = mu[g];
        out[NGRAPH * D + (b0 + g) * D + t]  = lv[g];
    }
}

// ---------------- launch ----------------
extern "C" void kernel_launch(void* const* d_in, const int* in_sizes, int n_in,
                              void* d_out, int out_size) {
    (void)in_sizes; (void)n_in; (void)out_size;
    const float* geometry   = (const float*)d_in[0];
    const int*   semantic   = (const int*)  d_in[1];
    const int*   edge_index = (const int*)  d_in[2];
    // d_in[3] = batch (unused: nodes are contiguous per graph)
    const float* W_geo = (const float*)d_in[4];
    const float* b_geo = (const float*)d_in[5];
    const float* emb   = (const float*)d_in[6];
    const float* W_lot = (const float*)d_in[7];
    const float* b_lot = (const float*)d_in[8];
    const float* W1    = (const float*)d_in[9];
    const float* b1    = (const float*)d_in[10];
    const float* W2    = (const float*)d_in[11];
    const float* b2    = (const float*)d_in[12];
    const float* W3    = (const float*)d_in[13];
    const float* b3    = (const float*)d_in[14];
    const float* W_agg = (const float*)d_in[15];
    const float* b_agg = (const float*)d_in[16];
    const float* W_mu  = (const float*)d_in[17];
    const float* b_mu  = (const float*)d_in[18];
    const float* W_var = (const float*)d_in[19];
    const float* b_var = (const float*)d_in[20];

    const size_t smem_main = SM_FLOATS * sizeof(float);                   // 64256 B
    const size_t smem_head = (GPB * 1024 + GPB * 256) * sizeof(float);    // 81920 B
    cudaFuncSetAttribute((const void*)gnn_main,
                         cudaFuncAttributeMaxDynamicSharedMemorySize, (int)smem_main);
    cudaFuncSetAttribute((const void*)head_kernel,
                         cudaFuncAttributeMaxDynamicSharedMemorySize, (int)smem_head);

    precompute_kernel<<<17, 256>>>(W_geo, b_geo, emb, W_lot, b_lot);
    gnn_main<<<NGRAPH, 256, smem_main>>>(geometry, semantic,
                                         edge_index, edge_index + NE,
                                         W_lot, W1, b1, W2, b2, W3, b3);
    head_kernel<<<NGRAPH / GPB, 256, smem_head>>>(W_agg, b_agg, W_mu, b_mu,
                                                  W_var, b_var, (float*)d_out);
}